// round 3
// baseline (speedup 1.0000x reference)
#include <cuda_runtime.h>
#include <math.h>

#define FULL 0xffffffffu

// ---------------- device scratch (no allocation) ----------------
__device__ float g_M1[128 * 128];
__device__ float g_qstate[32 * 16 * 128];
__device__ float g_qk[32 * 16 * 128];
__device__ float g_Spart[32 * 8 * 16 * 128];
__device__ float g_rspart[32 * 8 * 16];
__device__ float g_u[32 * 16 * 128];
__device__ float g_y[32 * 16 * 128];

static __device__ __forceinline__ float dot4(float4 a, float4 b) {
    return fmaf(a.x, b.x, fmaf(a.y, b.y, fmaf(a.z, b.z, a.w * b.w)));
}

// ---------------- init q state ----------------
__global__ void kcopy(const float* __restrict__ src) {
    int i = blockIdx.x * 128 + threadIdx.x;
    g_qstate[i] = src[i];
}

// ---------------- M1 = scale * Wq^T @ Wk ----------------
__global__ void kM1(const float* __restrict__ Wq, const float* __restrict__ Wk) {
    int e = blockIdx.x, d = threadIdx.x;
    float acc = 0.f;
    for (int c = 0; c < 128; c++)
        acc = fmaf(Wq[c * 128 + e], Wk[c * 128 + d], acc);
    g_M1[e * 128 + d] = acc * 0.08838834764831845f;  // 128^-0.5
}

// ---------------- qk = LN(qstate) @ M1 ----------------
__global__ void __launch_bounds__(128) kqk(const float* __restrict__ gq,
                                           const float* __restrict__ bq) {
    int b = blockIdx.x, t = threadIdx.x;
    int l = t & 31, w = t >> 5;
    __shared__ float xr[16][128];
    __shared__ float red[8];
    for (int r = 0; r < 16; r++) {
        float v = g_qstate[(b * 16 + r) * 128 + t];
        float s = v, s2 = v * v;
#pragma unroll
        for (int d = 16; d > 0; d >>= 1) {
            s  += __shfl_xor_sync(FULL, s, d);
            s2 += __shfl_xor_sync(FULL, s2, d);
        }
        if (l == 0) { red[w] = s; red[4 + w] = s2; }
        __syncthreads();
        s  = red[0] + red[1] + red[2] + red[3];
        s2 = red[4] + red[5] + red[6] + red[7];
        __syncthreads();
        float m = s * (1.f / 128.f);
        float rstd = rsqrtf(fmaf(s2, 1.f / 128.f, -m * m) + 1e-5f);
        xr[r][t] = fmaf((v - m) * rstd, gq[t], bq[t]);
    }
    __syncthreads();
    float acc[16];
#pragma unroll
    for (int r = 0; r < 16; r++) acc[r] = 0.f;
    for (int e = 0; e < 128; e++) {
        float mv = g_M1[e * 128 + t];
#pragma unroll
        for (int r = 0; r < 16; r++) acc[r] = fmaf(xr[r][e], mv, acc[r]);
    }
    for (int r = 0; r < 16; r++) g_qk[(b * 16 + r) * 128 + t] = acc[r];
}

// ---------------- streaming attention pass ----------------
// grid (8, 32), 256 threads. Warp handles 64 consecutive hw rows.
__global__ void __launch_bounds__(256) kstream(const float* __restrict__ inp,
                                               const float* __restrict__ lng,
                                               const float* __restrict__ lnb,
                                               float* __restrict__ a0out,
                                               int writeA0) {
    int p = blockIdx.x, b = blockIdx.y;
    int t = threadIdx.x, w = t >> 5, l = t & 31;
    __shared__ float a0buf[8][16][65];
    __shared__ float Sblk[16][128];
    __shared__ float rsblk[16];

    for (int i = t; i < 2048; i += 256) ((float*)Sblk)[i] = 0.f;
    if (t < 16) rsblk[t] = 0.f;

    float4 qkf[16];
    const float4* qkb = (const float4*)(g_qk + b * 2048);
#pragma unroll
    for (int q = 0; q < 16; q++) qkf[q] = qkb[q * 32 + l];
    float4 g4 = ((const float4*)lng)[l];
    float4 b4 = ((const float4*)lnb)[l];
    float4 Sa[16];
#pragma unroll
    for (int q = 0; q < 16; q++) { Sa[q].x = 0.f; Sa[q].y = 0.f; Sa[q].z = 0.f; Sa[q].w = 0.f; }
    float rsacc = 0.f;
    __syncthreads();

    int rowbase = p * 512 + w * 64;
    const float4* base = (const float4*)(inp + ((size_t)b * 4096 + rowbase) * 128);

    for (int i = 0; i < 64; i++) {
        float4 x = base[i * 32 + l];
        // LayerNorm of this 128-float row (on the fly -> kv row)
        float s  = x.x + x.y + x.z + x.w;
        float s2 = fmaf(x.x, x.x, fmaf(x.y, x.y, fmaf(x.z, x.z, x.w * x.w)));
#pragma unroll
        for (int d = 16; d > 0; d >>= 1) {
            s  += __shfl_xor_sync(FULL, s, d);
            s2 += __shfl_xor_sync(FULL, s2, d);
        }
        float m = s * (1.f / 128.f);
        float rstd = rsqrtf(fmaf(s2, 1.f / 128.f, -m * m) + 1e-5f);
        float4 xn;
        xn.x = fmaf((x.x - m) * rstd, g4.x, b4.x);
        xn.y = fmaf((x.y - m) * rstd, g4.y, b4.y);
        xn.z = fmaf((x.z - m) * rstd, g4.z, b4.z);
        xn.w = fmaf((x.w - m) * rstd, g4.w, b4.w);

        // per-lane partial logits vs all 16 slot queries
        float v[16];
#pragma unroll
        for (int q = 0; q < 16; q++) v[q] = dot4(xn, qkf[q]);

        // multi-value butterfly reduce: slot q's full sum lands at lanes 2q,2q+1
        float u8[8];
        {
            bool hi = (l & 16) != 0;
#pragma unroll
            for (int j = 0; j < 8; j++) {
                float mine = hi ? v[j + 8] : v[j];
                float oth  = hi ? v[j]     : v[j + 8];
                u8[j] = mine + __shfl_xor_sync(FULL, oth, 16);
            }
        }
        float u4[4];
        {
            bool hi = (l & 8) != 0;
#pragma unroll
            for (int j = 0; j < 4; j++) {
                float mine = hi ? u8[j + 4] : u8[j];
                float oth  = hi ? u8[j]     : u8[j + 4];
                u4[j] = mine + __shfl_xor_sync(FULL, oth, 8);
            }
        }
        float u2[2];
        {
            bool hi = (l & 4) != 0;
#pragma unroll
            for (int j = 0; j < 2; j++) {
                float mine = hi ? u4[j + 2] : u4[j];
                float oth  = hi ? u4[j]     : u4[j + 2];
                u2[j] = mine + __shfl_xor_sync(FULL, oth, 4);
            }
        }
        float u1;
        {
            bool hi = (l & 2) != 0;
            float mine = hi ? u2[1] : u2[0];
            float oth  = hi ? u2[0] : u2[1];
            u1 = mine + __shfl_xor_sync(FULL, oth, 2);
        }
        u1 += __shfl_xor_sync(FULL, u1, 1);
        float logit = u1;  // slot = l >> 1

        // softmax over the 16 slots (lanes with same bit0 cover all slots)
        float mx = logit;
#pragma unroll
        for (int d = 16; d >= 2; d >>= 1) mx = fmaxf(mx, __shfl_xor_sync(FULL, mx, d));
        float e = __expf(logit - mx);
        float sm = e;
#pragma unroll
        for (int d = 16; d >= 2; d >>= 1) sm += __shfl_xor_sync(FULL, sm, d);
        float a0v = e / sm;

        rsacc += a0v;                                   // per-slot rowsum partial
        if ((l & 1) == 0) a0buf[w][l >> 1][i] = a0v;    // buffer for coalesced flush

        // S[q][:] += a0[q] * kv_row
#pragma unroll
        for (int q = 0; q < 16; q++) {
            float aq = __shfl_sync(FULL, a0v, q * 2);
            Sa[q].x = fmaf(aq, xn.x, Sa[q].x);
            Sa[q].y = fmaf(aq, xn.y, Sa[q].y);
            Sa[q].z = fmaf(aq, xn.z, Sa[q].z);
            Sa[q].w = fmaf(aq, xn.w, Sa[q].w);
        }
    }

    __syncwarp();
    if (writeA0) {
        float* dst = a0out + ((size_t)b * 16) * 4096 + rowbase;
#pragma unroll
        for (int q = 0; q < 16; q++) {
            dst[(size_t)q * 4096 + l]      = a0buf[w][q][l];
            dst[(size_t)q * 4096 + 32 + l] = a0buf[w][q][32 + l];
        }
    }

    // block-level S reduction
#pragma unroll
    for (int q = 0; q < 16; q++) {
        atomicAdd(&Sblk[q][4 * l + 0], Sa[q].x);
        atomicAdd(&Sblk[q][4 * l + 1], Sa[q].y);
        atomicAdd(&Sblk[q][4 * l + 2], Sa[q].z);
        atomicAdd(&Sblk[q][4 * l + 3], Sa[q].w);
    }
    if ((l & 1) == 0) atomicAdd(&rsblk[l >> 1], rsacc);
    __syncthreads();

    float* sp = g_Spart + ((size_t)(b * 8 + p)) * 2048;
    for (int i = t; i < 2048; i += 256) sp[i] = ((float*)Sblk)[i];
    if (t < 16) g_rspart[(b * 8 + p) * 16 + t] = rsblk[t];
}

// ---------------- u = (S / (rowsum+eps)) @ Wv^T ----------------
__global__ void __launch_bounds__(128) ku(const float* __restrict__ Wv) {
    int b = blockIdx.x, t = threadIdx.x;
    __shared__ float sh[16][128];
    __shared__ float rs[16];
    for (int q = 0; q < 16; q++) {
        float acc = 0.f;
        for (int p = 0; p < 8; p++)
            acc += g_Spart[((size_t)(b * 8 + p)) * 2048 + q * 128 + t];
        sh[q][t] = acc;
    }
    if (t < 16) {
        float r = 0.f;
        for (int p = 0; p < 8; p++) r += g_rspart[(b * 8 + p) * 16 + t];
        rs[t] = 1.f / (r + 1e-5f);
    }
    __syncthreads();
    float acc[16];
#pragma unroll
    for (int q = 0; q < 16; q++) acc[q] = 0.f;
    const float4* wr = (const float4*)(Wv + t * 128);
    for (int db = 0; db < 32; db++) {
        float4 wv = wr[db];
#pragma unroll
        for (int q = 0; q < 16; q++) {
            float4 sv = ((const float4*)sh[q])[db];
            acc[q] = fmaf(sv.x, wv.x, fmaf(sv.y, wv.y, fmaf(sv.z, wv.z, fmaf(sv.w, wv.w, acc[q]))));
        }
    }
    float* uo = g_u + (b * 16) * 128 + t;
#pragma unroll
    for (int q = 0; q < 16; q++) uo[q * 128] = acc[q] * rs[q];
}

// ---------------- GRU cell: y = GRU(u, qstate) ----------------
__global__ void __launch_bounds__(128) kgru(const float* __restrict__ wih,
                                            const float* __restrict__ whh,
                                            const float* __restrict__ bih,
                                            const float* __restrict__ bhh) {
    int row0 = blockIdx.x * 4;
    int t = threadIdx.x;
    __shared__ float4 su[4][32], sx[4][32];
    ((float4*)su)[t] = ((const float4*)(g_u + row0 * 128))[t];
    ((float4*)sx)[t] = ((const float4*)(g_qstate + row0 * 128))[t];
    __syncthreads();
    int c = t;
    float aIR[4], aIZ[4], aIN[4], aHR[4], aHZ[4], aHN[4];
#pragma unroll
    for (int r = 0; r < 4; r++) { aIR[r]=0.f; aIZ[r]=0.f; aIN[r]=0.f; aHR[r]=0.f; aHZ[r]=0.f; aHN[r]=0.f; }
    const float4* wir = (const float4*)(wih + (size_t)c * 128);
    const float4* wiz = (const float4*)(wih + (size_t)(c + 128) * 128);
    const float4* win = (const float4*)(wih + (size_t)(c + 256) * 128);
    const float4* whr = (const float4*)(whh + (size_t)c * 128);
    const float4* whz = (const float4*)(whh + (size_t)(c + 128) * 128);
    const float4* whn = (const float4*)(whh + (size_t)(c + 256) * 128);
    for (int db = 0; db < 32; db++) {
        float4 wir4 = wir[db], wiz4 = wiz[db], win4 = win[db];
        float4 whr4 = whr[db], whz4 = whz[db], whn4 = whn[db];
#pragma unroll
        for (int r = 0; r < 4; r++) {
            float4 u4 = su[r][db], x4 = sx[r][db];
            aIR[r] += dot4(u4, wir4);
            aIZ[r] += dot4(u4, wiz4);
            aIN[r] += dot4(u4, win4);
            aHR[r] += dot4(x4, whr4);
            aHZ[r] += dot4(x4, whz4);
            aHN[r] += dot4(x4, whn4);
        }
    }
    float bi_r = bih[c], bi_z = bih[c + 128], bi_n = bih[c + 256];
    float bh_r = bhh[c], bh_z = bhh[c + 128], bh_n = bhh[c + 256];
#pragma unroll
    for (int r = 0; r < 4; r++) {
        float ir = aIR[r] + bi_r, iz = aIZ[r] + bi_z, in_ = aIN[r] + bi_n;
        float hr = aHR[r] + bh_r, hz = aHZ[r] + bh_z, hn = aHN[r] + bh_n;
        float rr = 1.f / (1.f + __expf(-(ir + hr)));
        float zz = 1.f / (1.f + __expf(-(iz + hz)));
        float nn = tanhf(in_ + rr * hn);
        float h = ((const float*)sx)[r * 128 + c];
        g_y[(row0 + r) * 128 + c] = (1.f - zz) * nn + zz * h;
    }
}

// ---------------- FFN: q = y + W2 relu(W1 LN(y) + b1) + b2 ----------------
__global__ void __launch_bounds__(128) kffn(const float* __restrict__ g2,
                                            const float* __restrict__ b2ln,
                                            const float* __restrict__ w1,
                                            const float* __restrict__ b1,
                                            const float* __restrict__ w2,
                                            const float* __restrict__ b2f,
                                            float* __restrict__ qout) {
    int row0 = blockIdx.x * 4;
    int t = threadIdx.x, w = t >> 5, l = t & 31;
    __shared__ float sz[4][128];
    __shared__ float sy[4][128];
    __shared__ float sh1[4][512];
    {
        float4 y4 = ((const float4*)(g_y + (row0 + w) * 128))[l];
        float s  = y4.x + y4.y + y4.z + y4.w;
        float s2 = fmaf(y4.x, y4.x, fmaf(y4.y, y4.y, fmaf(y4.z, y4.z, y4.w * y4.w)));
#pragma unroll
        for (int d = 16; d > 0; d >>= 1) {
            s  += __shfl_xor_sync(FULL, s, d);
            s2 += __shfl_xor_sync(FULL, s2, d);
        }
        float m = s * (1.f / 128.f);
        float rstd = rsqrtf(fmaf(s2, 1.f / 128.f, -m * m) + 1e-5f);
        float4 gg = ((const float4*)g2)[l], bb = ((const float4*)b2ln)[l];
        float4 z4;
        z4.x = fmaf((y4.x - m) * rstd, gg.x, bb.x);
        z4.y = fmaf((y4.y - m) * rstd, gg.y, bb.y);
        z4.z = fmaf((y4.z - m) * rstd, gg.z, bb.z);
        z4.w = fmaf((y4.w - m) * rstd, gg.w, bb.w);
        ((float4*)sz[w])[l] = z4;
        ((float4*)sy[w])[l] = y4;
    }
    __syncthreads();
    {
        float acc[4][4];
#pragma unroll
        for (int r = 0; r < 4; r++)
#pragma unroll
            for (int oj = 0; oj < 4; oj++) acc[r][oj] = 0.f;
        const float4* w1p0 = (const float4*)(w1 + (size_t)t * 128);
        const float4* w1p1 = (const float4*)(w1 + (size_t)(t + 128) * 128);
        const float4* w1p2 = (const float4*)(w1 + (size_t)(t + 256) * 128);
        const float4* w1p3 = (const float4*)(w1 + (size_t)(t + 384) * 128);
        for (int db = 0; db < 32; db++) {
            float4 wv0 = w1p0[db], wv1 = w1p1[db], wv2 = w1p2[db], wv3 = w1p3[db];
#pragma unroll
            for (int r = 0; r < 4; r++) {
                float4 zz = ((const float4*)sz[r])[db];
                acc[r][0] += dot4(zz, wv0);
                acc[r][1] += dot4(zz, wv1);
                acc[r][2] += dot4(zz, wv2);
                acc[r][3] += dot4(zz, wv3);
            }
        }
#pragma unroll
        for (int r = 0; r < 4; r++)
#pragma unroll
            for (int oj = 0; oj < 4; oj++)
                sh1[r][t + oj * 128] = fmaxf(acc[r][oj] + b1[t + oj * 128], 0.f);
    }
    __syncthreads();
    {
        float acc[4];
#pragma unroll
        for (int r = 0; r < 4; r++) acc[r] = 0.f;
        const float4* w2p = (const float4*)(w2 + (size_t)t * 512);
        for (int db = 0; db < 128; db++) {
            float4 wv = w2p[db];
#pragma unroll
            for (int r = 0; r < 4; r++) {
                float4 hh = ((const float4*)sh1[r])[db];
                acc[r] += dot4(hh, wv);
            }
        }
        float bb = b2f[t];
#pragma unroll
        for (int r = 0; r < 4; r++) {
            float val = sy[r][t] + acc[r] + bb;
            g_qstate[(row0 + r) * 128 + t] = val;
            if (qout) qout[(row0 + r) * 128 + t] = val;
        }
    }
}

extern "C" void kernel_launch(void* const* d_in, const int* in_sizes, int n_in,
                              void* d_out, int out_size) {
    const float* inp      = (const float*)d_in[0];
    const float* query    = (const float*)d_in[1];
    const float* ln_kv_g  = (const float*)d_in[2];
    const float* ln_kv_b  = (const float*)d_in[3];
    const float* Wk       = (const float*)d_in[4];
    const float* Wv       = (const float*)d_in[5];
    const float* ln_q_g   = (const float*)d_in[6];
    const float* ln_q_b   = (const float*)d_in[7];
    const float* Wq       = (const float*)d_in[8];
    const float* gru_wih  = (const float*)d_in[9];
    const float* gru_whh  = (const float*)d_in[10];
    const float* gru_bih  = (const float*)d_in[11];
    const float* gru_bhh  = (const float*)d_in[12];
    const float* ln2_g    = (const float*)d_in[13];
    const float* ln2_b    = (const float*)d_in[14];
    const float* ffn_w1   = (const float*)d_in[15];
    const float* ffn_b1   = (const float*)d_in[16];
    const float* ffn_w2   = (const float*)d_in[17];
    const float* ffn_b2   = (const float*)d_in[18];

    float* out   = (float*)d_out;           // q: 32*16*128
    float* a0out = out + 32 * 16 * 128;     // a0: 32*16*4096

    kM1<<<128, 128>>>(Wq, Wk);
    kcopy<<<512, 128>>>(query);
    for (int it = 0; it < 3; it++) {
        int last = (it == 2);
        kqk<<<32, 128>>>(ln_q_g, ln_q_b);
        kstream<<<dim3(8, 32), 256>>>(inp, ln_kv_g, ln_kv_b, a0out, last);
        ku<<<32, 128>>>(Wv);
        kgru<<<128, 128>>>(gru_wih, gru_whh, gru_bih, gru_bhh);
        kffn<<<128, 128>>>(ln2_g, ln2_b, ffn_w1, ffn_b1, ffn_w2, ffn_b2,
                           last ? out : (float*)nullptr);
    }
}

// round 4
// speedup vs baseline: 1.0198x; 1.0198x over previous
#include <cuda_runtime.h>
#include <math.h>
#define FULL 0xffffffffu

__device__ float g_M1[128*128];
__device__ float g_qstate[32*16*128];
__device__ float g_qkg[32*16*128];
__device__ float g_cq1[32*16];
__device__ float g_cq0[32*16];
__device__ float g_Tpart[32*8*16*128];
__device__ float g_t1p[32*8*16];
__device__ float g_t2p[32*8*16];
__device__ float g_u[32*16*128];
__device__ float g_y[32*16*128];

static __device__ __forceinline__ float dot4(float4 a, float4 b) {
    return fmaf(a.x,b.x,fmaf(a.y,b.y,fmaf(a.z,b.z,a.w*b.w)));
}
// sums v[0..15] over 32 lanes; slot q total lands on lanes 2q,2q+1
static __device__ __forceinline__ float butterfly16(const float* v, int l) {
    float u8[8];
    { bool hi=(l&16);
#pragma unroll
      for(int j=0;j<8;j++){float mi=hi?v[j+8]:v[j],ot=hi?v[j]:v[j+8];
        u8[j]=mi+__shfl_xor_sync(FULL,ot,16);} }
    float u4[4];
    { bool hi=(l&8);
#pragma unroll
      for(int j=0;j<4;j++){float mi=hi?u8[j+4]:u8[j],ot=hi?u8[j]:u8[j+4];
        u4[j]=mi+__shfl_xor_sync(FULL,ot,8);} }
    float u2[2];
    { bool hi=(l&4);
#pragma unroll
      for(int j=0;j<2;j++){float mi=hi?u4[j+2]:u4[j],ot=hi?u4[j]:u4[j+2];
        u2[j]=mi+__shfl_xor_sync(FULL,ot,4);} }
    float u1;
    { bool hi=(l&2);
      float mi=hi?u2[1]:u2[0],ot=hi?u2[0]:u2[1];
      u1=mi+__shfl_xor_sync(FULL,ot,2); }
    return u1+__shfl_xor_sync(FULL,u1,1);
}
// exp via FMA-pipe polynomial (no MUFU)
static __device__ __forceinline__ float fexp(float x) {
    x = fmaxf(x, -87.f);
    float t = fmaf(x, 1.4426950408889634f, 12582912.f);
    int ni = __float_as_int(t) - 0x4B400000;
    float n = t - 12582912.f;
    float f = fmaf(x, 1.4426950408889634f, -n);
    float p = 1.5403530e-4f;
    p = fmaf(p,f,1.3333558e-3f); p = fmaf(p,f,9.6181291e-3f);
    p = fmaf(p,f,5.5504109e-2f); p = fmaf(p,f,2.4022651e-1f);
    p = fmaf(p,f,6.9314718e-1f); p = fmaf(p,f,1.f);
    return p * __int_as_float((ni + 127) << 23);
}

__global__ void kcopy(const float* __restrict__ s){
    int i = blockIdx.x*128+threadIdx.x; g_qstate[i]=s[i];
}
__global__ void kM1(const float* __restrict__ Wq, const float* __restrict__ Wk){
    int e=blockIdx.x, d=threadIdx.x; float a=0.f;
    for(int c=0;c<128;c++) a=fmaf(Wq[c*128+e],Wk[c*128+d],a);
    g_M1[e*128+d]=a*0.08838834764831845f;
}

// qkg = (LN(q)@M1)*g_kv ; cq1 = sum(qkg) ; cq0 = (LN(q)@M1).b_kv
__global__ void __launch_bounds__(128) kqk(const float* __restrict__ gq,
        const float* __restrict__ bq, const float* __restrict__ gkv,
        const float* __restrict__ bkv){
    int b=blockIdx.x, t=threadIdx.x, l=t&31, w=t>>5;
    __shared__ float xr[16][128], qb[16][128], red[8];
    for(int r=0;r<16;r++){
        float v=g_qstate[(b*16+r)*128+t];
        float s=v,s2=v*v;
#pragma unroll
        for(int d=16;d>0;d>>=1){s+=__shfl_xor_sync(FULL,s,d);s2+=__shfl_xor_sync(FULL,s2,d);}
        if(l==0){red[w]=s;red[4+w]=s2;}
        __syncthreads();
        s=red[0]+red[1]+red[2]+red[3]; s2=red[4]+red[5]+red[6]+red[7];
        __syncthreads();
        float m=s*(1.f/128.f);
        float rstd=rsqrtf(fmaf(s2,1.f/128.f,-m*m)+1e-5f);
        xr[r][t]=fmaf((v-m)*rstd,gq[t],bq[t]);
    }
    __syncthreads();
    float acc[16];
#pragma unroll
    for(int r=0;r<16;r++) acc[r]=0.f;
    for(int e=0;e<128;e++){
        float mv=g_M1[e*128+t];
#pragma unroll
        for(int r=0;r<16;r++) acc[r]=fmaf(xr[r][e],mv,acc[r]);
    }
    __syncthreads();
    float gv=gkv[t], bv=bkv[t];
    for(int r=0;r<16;r++){
        float qg=acc[r]*gv;
        g_qkg[(b*16+r)*128+t]=qg;
        xr[r][t]=qg; qb[r][t]=acc[r]*bv;
    }
    __syncthreads();
    if(t<16){
        float c1=0.f,c0=0.f;
        for(int c=0;c<128;c++){c1+=xr[t][c];c0+=qb[t][c];}
        g_cq1[b*16+t]=c1; g_cq0[b*16+t]=c0;
    }
}

// fused stream: grid(8,32), 256 thr, 2 CTA/SM
__global__ void __launch_bounds__(256,2) kstream3(const float* __restrict__ inp,
        float* __restrict__ a0out, int writeA0){
    __shared__ float dbuf[512*17];     // logits then w
    __shared__ float rstd_s[512], m_s[512];
    __shared__ float4 qks[16][32];     // phase1: qkg ; phase3: reused as Sblk
    __shared__ float t1s[16], t2s[16];
    float* Sblk = (float*)qks;
    int p=blockIdx.x, b=blockIdx.y, t=threadIdx.x, w=t>>5, l=t&31;

    if(t<16){t1s[t]=0.f;t2s[t]=0.f;}
#pragma unroll
    for(int k=0;k<8;k++) ((float*)qks)[k*256+t]=g_qkg[b*2048+k*256+t];
    __syncthreads();

    // phase 1: raw dots + LN stats -> logits
    {
        float cq1v=g_cq1[b*16+(l>>1)], cq0v=g_cq0[b*16+(l>>1)];
        int rb=w*64;
        const float4* base=(const float4*)(inp+((size_t)b*4096+p*512+rb)*128);
        for(int i=0;i<64;i++){
            float4 x=base[i*32+l];
            float s=x.x+x.y+x.z+x.w;
            float s2=fmaf(x.x,x.x,fmaf(x.y,x.y,fmaf(x.z,x.z,x.w*x.w)));
            float v[16];
#pragma unroll
            for(int q=0;q<16;q++) v[q]=dot4(x,qks[q][l]);
#pragma unroll
            for(int d=16;d>0;d>>=1){s+=__shfl_xor_sync(FULL,s,d);s2+=__shfl_xor_sync(FULL,s2,d);}
            float u1=butterfly16(v,l);
            float m=s*(1.f/128.f);
            float rs=rsqrtf(fmaf(s2,1.f/128.f,-m*m)+1e-5f);
            int row=rb+i;
            if((l&1)==0) dbuf[row*17+(l>>1)]=fmaf(rs,fmaf(-m,cq1v,u1),cq0v);
            if(l==0){rstd_s[row]=rs;m_s[row]=m;}
        }
    }
    __syncthreads();

    // phase 2: softmax per row (thread=row), w=a0*rstd, t1/t2
    for(int j=0;j<2;j++){
        int r=t+j*256;
        float rs=rstd_s[r], mv=m_s[r];
        float a0[16], mx=-1e30f;
#pragma unroll
        for(int q=0;q<16;q++){a0[q]=dbuf[r*17+q]; mx=fmaxf(mx,a0[q]);}
        float ssum=0.f;
#pragma unroll
        for(int q=0;q<16;q++){a0[q]=fexp(a0[q]-mx); ssum+=a0[q];}
        float inv=1.f/ssum;
        float t1v[16];
#pragma unroll
        for(int q=0;q<16;q++){
            a0[q]*=inv;
            dbuf[r*17+q]=a0[q]*rs;
            t1v[q]=a0[q]*rs*mv;
        }
        float t2r=butterfly16(a0,l), t1r=butterfly16(t1v,l);
        if((l&1)==0){atomicAdd(&t2s[l>>1],t2r);atomicAdd(&t1s[l>>1],t1r);}
        if(writeA0){
            float* dst=a0out+(size_t)b*65536+p*512+j*256+t;
#pragma unroll
            for(int q=0;q<16;q++) dst[(size_t)q*4096]=a0[q];
        }
    }
    __syncthreads();

    // phase 3: S += w * x (chain-free)
    for(int i=t;i<2048;i+=256) Sblk[i]=0.f;
    __syncthreads();
    {
        float4 Sa[16];
#pragma unroll
        for(int q=0;q<16;q++){Sa[q].x=0.f;Sa[q].y=0.f;Sa[q].z=0.f;Sa[q].w=0.f;}
        int rb=w*64;
        const float4* base=(const float4*)(inp+((size_t)b*4096+p*512+rb)*128);
        const float* wb=dbuf+rb*17;
        for(int i=0;i<64;i++){
            float4 x=base[i*32+l];
            const float* wr=wb+i*17;
#pragma unroll
            for(int q=0;q<16;q++){
                float wq=wr[q];
                Sa[q].x=fmaf(wq,x.x,Sa[q].x); Sa[q].y=fmaf(wq,x.y,Sa[q].y);
                Sa[q].z=fmaf(wq,x.z,Sa[q].z); Sa[q].w=fmaf(wq,x.w,Sa[q].w);
            }
        }
#pragma unroll
        for(int q=0;q<16;q++){
            atomicAdd(&Sblk[q*128+4*l+0],Sa[q].x);
            atomicAdd(&Sblk[q*128+4*l+1],Sa[q].y);
            atomicAdd(&Sblk[q*128+4*l+2],Sa[q].z);
            atomicAdd(&Sblk[q*128+4*l+3],Sa[q].w);
        }
    }
    __syncthreads();
    float* tp=g_Tpart+((size_t)(b*8+p))*2048;
    for(int i=t;i<2048;i+=256) tp[i]=Sblk[i];
    if(t<16){g_t1p[(b*8+p)*16+t]=t1s[t];g_t2p[(b*8+p)*16+t]=t2s[t];}
}

// u = ((g*(S-t1)+b*t2)/(t2+eps)) @ Wv^T
__global__ void __launch_bounds__(128) ku(const float* __restrict__ Wv,
        const float* __restrict__ gkv, const float* __restrict__ bkv){
    int b=blockIdx.x, t=threadIdx.x;
    __shared__ float sh[16][128], rs[16], t1a[16], t2a[16];
    if(t<16){
        float s1=0.f,s2=0.f;
        for(int p=0;p<8;p++){s1+=g_t1p[(b*8+p)*16+t];s2+=g_t2p[(b*8+p)*16+t];}
        t1a[t]=s1;t2a[t]=s2;rs[t]=1.f/(s2+1e-5f);
    }
    __syncthreads();
    float gv=gkv[t], bv=bkv[t];
    for(int q=0;q<16;q++){
        float a=0.f;
        for(int p=0;p<8;p++) a+=g_Tpart[((size_t)(b*8+p))*2048+q*128+t];
        sh[q][t]=fmaf(gv,a-t1a[q],bv*t2a[q]);
    }
    __syncthreads();
    float acc[16];
#pragma unroll
    for(int q=0;q<16;q++) acc[q]=0.f;
    const float4* wr=(const float4*)(Wv+t*128);
    for(int d=0;d<32;d++){
        float4 wv=wr[d];
#pragma unroll
        for(int q=0;q<16;q++) acc[q]+=dot4(((const float4*)sh[q])[d],wv);
    }
    float* uo=g_u+(b*16)*128+t;
#pragma unroll
    for(int q=0;q<16;q++) uo[q*128]=acc[q]*rs[q];
}

// GRU: 64 blocks x 256 thr, 8 rows/block
__global__ void __launch_bounds__(256) kgru(const float* __restrict__ wih,
        const float* __restrict__ whh, const float* __restrict__ bih,
        const float* __restrict__ bhh){
    int row0=blockIdx.x*8, t=threadIdx.x;
    __shared__ float su[8][128], sx[8][128];
#pragma unroll
    for(int k=0;k<4;k++){
        ((float*)su)[k*256+t]=g_u[row0*128+k*256+t];
        ((float*)sx)[k*256+t]=g_qstate[row0*128+k*256+t];
    }
    __syncthreads();
    int c=t&127, rh=(t>>7)*4;
    float aIR[4],aIZ[4],aIN[4],aHR[4],aHZ[4],aHN[4];
#pragma unroll
    for(int k=0;k<4;k++){aIR[k]=0;aIZ[k]=0;aIN[k]=0;aHR[k]=0;aHZ[k]=0;aHN[k]=0;}
    const float4* wir=(const float4*)(wih+(size_t)c*128);
    const float4* wiz=(const float4*)(wih+(size_t)(c+128)*128);
    const float4* win=(const float4*)(wih+(size_t)(c+256)*128);
    const float4* whr=(const float4*)(whh+(size_t)c*128);
    const float4* whz=(const float4*)(whh+(size_t)(c+128)*128);
    const float4* whn=(const float4*)(whh+(size_t)(c+256)*128);
    for(int d=0;d<32;d++){
        float4 w0=wir[d],w1=wiz[d],w2=win[d],w3=whr[d],w4=whz[d],w5=whn[d];
#pragma unroll
        for(int k=0;k<4;k++){
            float4 u4=((const float4*)su[rh+k])[d], x4=((const float4*)sx[rh+k])[d];
            aIR[k]+=dot4(u4,w0); aIZ[k]+=dot4(u4,w1); aIN[k]+=dot4(u4,w2);
            aHR[k]+=dot4(x4,w3); aHZ[k]+=dot4(x4,w4); aHN[k]+=dot4(x4,w5);
        }
    }
    float bir=bih[c],biz=bih[c+128],bin=bih[c+256];
    float bhr=bhh[c],bhz=bhh[c+128],bhn=bhh[c+256];
#pragma unroll
    for(int k=0;k<4;k++){
        float rr=1.f/(1.f+fexp(-(aIR[k]+bir+aHR[k]+bhr)));
        float zz=1.f/(1.f+fexp(-(aIZ[k]+biz+aHZ[k]+bhz)));
        float nn=tanhf(aIN[k]+bin+rr*(aHN[k]+bhn));
        float h=sx[rh+k][c];
        g_y[(row0+rh+k)*128+c]=(1.f-zz)*nn+zz*h;
    }
}

// FFN: 64 blocks x 256 thr, 8 rows/block
__global__ void __launch_bounds__(256) kffn(const float* __restrict__ g2,
        const float* __restrict__ b2ln, const float* __restrict__ w1,
        const float* __restrict__ b1, const float* __restrict__ w2,
        const float* __restrict__ b2f, float* __restrict__ qout){
    int row0=blockIdx.x*8, t=threadIdx.x, w=t>>5, l=t&31;
    __shared__ float sz[8][128], sy[8][128], sh1[8][512];
    {
        float4 y4=((const float4*)(g_y+(row0+w)*128))[l];
        float s=y4.x+y4.y+y4.z+y4.w;
        float s2=fmaf(y4.x,y4.x,fmaf(y4.y,y4.y,fmaf(y4.z,y4.z,y4.w*y4.w)));
#pragma unroll
        for(int d=16;d>0;d>>=1){s+=__shfl_xor_sync(FULL,s,d);s2+=__shfl_xor_sync(FULL,s2,d);}
        float m=s*(1.f/128.f);
        float rstd=rsqrtf(fmaf(s2,1.f/128.f,-m*m)+1e-5f);
        float4 gg=((const float4*)g2)[l], bb=((const float4*)b2ln)[l];
        float4 z4;
        z4.x=fmaf((y4.x-m)*rstd,gg.x,bb.x); z4.y=fmaf((y4.y-m)*rstd,gg.y,bb.y);
        z4.z=fmaf((y4.z-m)*rstd,gg.z,bb.z); z4.w=fmaf((y4.w-m)*rstd,gg.w,bb.w);
        ((float4*)sz[w])[l]=z4; ((float4*)sy[w])[l]=y4;
    }
    __syncthreads();
    {
        float acc[2][8];
#pragma unroll
        for(int j=0;j<2;j++)
#pragma unroll
            for(int r=0;r<8;r++) acc[j][r]=0.f;
        const float4* wa=(const float4*)(w1+(size_t)t*128);
        const float4* wb=(const float4*)(w1+(size_t)(t+256)*128);
        for(int d=0;d<32;d++){
            float4 a=wa[d], b=wb[d];
#pragma unroll
            for(int r=0;r<8;r++){
                float4 zz=((const float4*)sz[r])[d];
                acc[0][r]+=dot4(zz,a); acc[1][r]+=dot4(zz,b);
            }
        }
        float b0=b1[t], b256=b1[t+256];
#pragma unroll
        for(int r=0;r<8;r++){
            sh1[r][t]=fmaxf(acc[0][r]+b0,0.f);
            sh1[r][t+256]=fmaxf(acc[1][r]+b256,0.f);
        }
    }
    __syncthreads();
    {
        int c=t&127, rh=(t>>7)*4;
        float acc[4];
#pragma unroll
        for(int k=0;k<4;k++) acc[k]=0.f;
        const float4* wp=(const float4*)(w2+(size_t)c*512);
        for(int d=0;d<128;d++){
            float4 wv=wp[d];
#pragma unroll
            for(int k=0;k<4;k++) acc[k]+=dot4(((const float4*)sh1[rh+k])[d],wv);
        }
        float bb=b2f[c];
#pragma unroll
        for(int k=0;k<4;k++){
            float val=sy[rh+k][c]+acc[k]+bb;
            g_qstate[(row0+rh+k)*128+c]=val;
            if(qout) qout[(row0+rh+k)*128+c]=val;
        }
    }
}

extern "C" void kernel_launch(void* const* d_in, const int* in_sizes, int n_in,
                              void* d_out, int out_size){
    const float* inp=(const float*)d_in[0];
    const float* query=(const float*)d_in[1];
    const float* ln_kv_g=(const float*)d_in[2];
    const float* ln_kv_b=(const float*)d_in[3];
    const float* Wk=(const float*)d_in[4];
    const float* Wv=(const float*)d_in[5];
    const float* ln_q_g=(const float*)d_in[6];
    const float* ln_q_b=(const float*)d_in[7];
    const float* Wq=(const float*)d_in[8];
    const float* gru_wih=(const float*)d_in[9];
    const float* gru_whh=(const float*)d_in[10];
    const float* gru_bih=(const float*)d_in[11];
    const float* gru_bhh=(const float*)d_in[12];
    const float* ln2_g=(const float*)d_in[13];
    const float* ln2_b=(const float*)d_in[14];
    const float* ffn_w1=(const float*)d_in[15];
    const float* ffn_b1=(const float*)d_in[16];
    const float* ffn_w2=(const float*)d_in[17];
    const float* ffn_b2=(const float*)d_in[18];
    float* out=(float*)d_out;
    float* a0out=out+32*16*128;

    kM1<<<128,128>>>(Wq,Wk);
    kcopy<<<512,128>>>(query);
    for(int it=0;it<3;it++){
        int last=(it==2);
        kqk<<<32,128>>>(ln_q_g,ln_q_b,ln_kv_g,ln_kv_b);
        kstream3<<<dim3(8,32),256>>>(inp,a0out,last);
        ku<<<32,128>>>(Wv,ln_kv_g,ln_kv_b);
        kgru<<<64,256>>>(gru_wih,gru_whh,gru_bih,gru_bhh);
        kffn<<<64,256>>>(ln2_g,ln2_b,ffn_w1,ffn_b1,ffn_w2,ffn_b2,
                         last?out:(float*)nullptr);
    }
}

// round 5
// speedup vs baseline: 1.2692x; 1.2445x over previous
#include <cuda_runtime.h>
#include <math.h>
#define FULL 0xffffffffu

__device__ float g_M1[128*128];
__device__ float g_qstate[32*16*128];
__device__ float g_qkg[32*16*128];
__device__ float g_cq1[32*16];
__device__ float g_cq0[32*16];
__device__ float g_Tpart[32*8*16*128];
__device__ float g_t1p[32*8*16];
__device__ float g_t2p[32*8*16];

static __device__ __forceinline__ float dot4(float4 a, float4 b) {
    return fmaf(a.x,b.x,fmaf(a.y,b.y,fmaf(a.z,b.z,a.w*b.w)));
}
static __device__ __forceinline__ float butterfly16(const float* v, int l) {
    float u8[8];
    { bool hi=(l&16);
#pragma unroll
      for(int j=0;j<8;j++){float mi=hi?v[j+8]:v[j],ot=hi?v[j]:v[j+8];
        u8[j]=mi+__shfl_xor_sync(FULL,ot,16);} }
    float u4[4];
    { bool hi=(l&8);
#pragma unroll
      for(int j=0;j<4;j++){float mi=hi?u8[j+4]:u8[j],ot=hi?u8[j]:u8[j+4];
        u4[j]=mi+__shfl_xor_sync(FULL,ot,8);} }
    float u2[2];
    { bool hi=(l&4);
#pragma unroll
      for(int j=0;j<2;j++){float mi=hi?u4[j+2]:u4[j],ot=hi?u4[j]:u4[j+2];
        u2[j]=mi+__shfl_xor_sync(FULL,ot,4);} }
    float u1;
    { bool hi=(l&2);
      float mi=hi?u2[1]:u2[0],ot=hi?u2[0]:u2[1];
      u1=mi+__shfl_xor_sync(FULL,ot,2); }
    return u1+__shfl_xor_sync(FULL,u1,1);
}
static __device__ __forceinline__ float fexp(float x) {
    x = fmaxf(x, -87.f);
    float t = fmaf(x, 1.4426950408889634f, 12582912.f);
    int ni = __float_as_int(t) - 0x4B400000;
    float n = t - 12582912.f;
    float f = fmaf(x, 1.4426950408889634f, -n);
    float p = 1.5403530e-4f;
    p = fmaf(p,f,1.3333558e-3f); p = fmaf(p,f,9.6181291e-3f);
    p = fmaf(p,f,5.5504109e-2f); p = fmaf(p,f,2.4022651e-1f);
    p = fmaf(p,f,6.9314718e-1f); p = fmaf(p,f,1.f);
    return p * __int_as_float((ni + 127) << 23);
}

__global__ void kcopy(const float* __restrict__ s){
    int i = blockIdx.x*128+threadIdx.x; g_qstate[i]=s[i];
}
__global__ void kM1(const float* __restrict__ Wq, const float* __restrict__ Wk){
    int e=blockIdx.x, d=threadIdx.x; float a=0.f;
    for(int c=0;c<128;c++) a=fmaf(Wq[c*128+e],Wk[c*128+d],a);
    g_M1[e*128+d]=a*0.08838834764831845f;
}

// shared tail helper: given qnew rows in sq[8][128], produce z=LN*gq+bq into sz
static __device__ __forceinline__ void ln_rows8(const float (*sq)[128], float (*sz)[128],
        const float* gq, const float* bq, int w, int l){
    float4 y4=((const float4*)sq[w])[l];
    float s=y4.x+y4.y+y4.z+y4.w;
    float s2=fmaf(y4.x,y4.x,fmaf(y4.y,y4.y,fmaf(y4.z,y4.z,y4.w*y4.w)));
#pragma unroll
    for(int d=16;d>0;d>>=1){s+=__shfl_xor_sync(FULL,s,d);s2+=__shfl_xor_sync(FULL,s2,d);}
    float m=s*(1.f/128.f);
    float rstd=rsqrtf(fmaf(s2,1.f/128.f,-m*m)+1e-5f);
    float4 gg=((const float4*)gq)[l], bb=((const float4*)bq)[l];
    float4 z4;
    z4.x=fmaf((y4.x-m)*rstd,gg.x,bb.x); z4.y=fmaf((y4.y-m)*rstd,gg.y,bb.y);
    z4.z=fmaf((y4.z-m)*rstd,gg.z,bb.z); z4.w=fmaf((y4.w-m)*rstd,gg.w,bb.w);
    ((float4*)sz[w])[l]=z4;
}
// qk projection: sz rows -> qkraw -> g_qkg/cq1/cq0 for rows qbase..qbase+7
static __device__ __forceinline__ void qkproj(const float (*sz)[128], float (*qkraw)[128],
        const float* gkv, const float* bkv, int qbase, int t, int w, int l){
    int c=t&127, rq=(t>>7)*4;
    float acc[4]={0.f,0.f,0.f,0.f};
    for(int e=0;e<128;e++){
        float mv=g_M1[e*128+c];
#pragma unroll
        for(int k=0;k<4;k++) acc[k]=fmaf(sz[rq+k][e],mv,acc[k]);
    }
#pragma unroll
    for(int k=0;k<4;k++) qkraw[rq+k][c]=acc[k];
    __syncthreads();
    float4 qr=((const float4*)qkraw[w])[l];
    float4 g4=((const float4*)gkv)[l], b4=((const float4*)bkv)[l];
    float c1=dot4(qr,g4), c0=dot4(qr,b4);
#pragma unroll
    for(int d=16;d>0;d>>=1){c1+=__shfl_xor_sync(FULL,c1,d);c0+=__shfl_xor_sync(FULL,c0,d);}
    if(l==0){g_cq1[qbase+w]=c1; g_cq0[qbase+w]=c0;}
    float4 o; o.x=qr.x*g4.x; o.y=qr.y*g4.y; o.z=qr.z*g4.z; o.w=qr.w*g4.w;
    ((float4*)(g_qkg+(qbase+w)*128))[l]=o;
}

// initial qkg/cq from qstate: grid 64 x 256
__global__ void __launch_bounds__(256) kqk0(const float* __restrict__ gq,
        const float* __restrict__ bq, const float* __restrict__ gkv,
        const float* __restrict__ bkv){
    int blk=blockIdx.x, t=threadIdx.x, w=t>>5, l=t&31;
    int qbase=blk*8;
    __shared__ float sq[8][128], sz[8][128], qkraw[8][128];
#pragma unroll
    for(int k=0;k<4;k++) ((float*)sq)[k*256+t]=g_qstate[qbase*128+k*256+t];
    __syncthreads();
    ln_rows8(sq,sz,gq,bq,w,l);
    __syncthreads();
    qkproj(sz,qkraw,gkv,bkv,qbase,t,w,l);
}

// ---- kstream3: unchanged from R4 (known good, 76us) ----
__global__ void __launch_bounds__(256,2) kstream3(const float* __restrict__ inp,
        float* __restrict__ a0out, int writeA0){
    __shared__ float dbuf[512*17];
    __shared__ float rstd_s[512], m_s[512];
    __shared__ float4 qks[16][32];
    __shared__ float t1s[16], t2s[16];
    float* Sblk = (float*)qks;
    int p=blockIdx.x, b=blockIdx.y, t=threadIdx.x, w=t>>5, l=t&31;
    if(t<16){t1s[t]=0.f;t2s[t]=0.f;}
#pragma unroll
    for(int k=0;k<8;k++) ((float*)qks)[k*256+t]=g_qkg[b*2048+k*256+t];
    __syncthreads();
    {
        float cq1v=g_cq1[b*16+(l>>1)], cq0v=g_cq0[b*16+(l>>1)];
        int rb=w*64;
        const float4* base=(const float4*)(inp+((size_t)b*4096+p*512+rb)*128);
        for(int i=0;i<64;i++){
            float4 x=base[i*32+l];
            float s=x.x+x.y+x.z+x.w;
            float s2=fmaf(x.x,x.x,fmaf(x.y,x.y,fmaf(x.z,x.z,x.w*x.w)));
            float v[16];
#pragma unroll
            for(int q=0;q<16;q++) v[q]=dot4(x,qks[q][l]);
#pragma unroll
            for(int d=16;d>0;d>>=1){s+=__shfl_xor_sync(FULL,s,d);s2+=__shfl_xor_sync(FULL,s2,d);}
            float u1=butterfly16(v,l);
            float m=s*(1.f/128.f);
            float rs=rsqrtf(fmaf(s2,1.f/128.f,-m*m)+1e-5f);
            int row=rb+i;
            if((l&1)==0) dbuf[row*17+(l>>1)]=fmaf(rs,fmaf(-m,cq1v,u1),cq0v);
            if(l==0){rstd_s[row]=rs;m_s[row]=m;}
        }
    }
    __syncthreads();
    for(int j=0;j<2;j++){
        int r=t+j*256;
        float rs=rstd_s[r], mv=m_s[r];
        float a0[16], mx=-1e30f;
#pragma unroll
        for(int q=0;q<16;q++){a0[q]=dbuf[r*17+q]; mx=fmaxf(mx,a0[q]);}
        float ssum=0.f;
#pragma unroll
        for(int q=0;q<16;q++){a0[q]=fexp(a0[q]-mx); ssum+=a0[q];}
        float inv=1.f/ssum;
        float t1v[16];
#pragma unroll
        for(int q=0;q<16;q++){
            a0[q]*=inv;
            dbuf[r*17+q]=a0[q]*rs;
            t1v[q]=a0[q]*rs*mv;
        }
        float t2r=butterfly16(a0,l), t1r=butterfly16(t1v,l);
        if((l&1)==0){atomicAdd(&t2s[l>>1],t2r);atomicAdd(&t1s[l>>1],t1r);}
        if(writeA0){
            float* dst=a0out+(size_t)blockIdx.y*65536+blockIdx.x*512+j*256+t;
#pragma unroll
            for(int q=0;q<16;q++) dst[(size_t)q*4096]=a0[q];
        }
    }
    __syncthreads();
    for(int i=t;i<2048;i+=256) Sblk[i]=0.f;
    __syncthreads();
    {
        float4 Sa[16];
#pragma unroll
        for(int q=0;q<16;q++){Sa[q].x=0.f;Sa[q].y=0.f;Sa[q].z=0.f;Sa[q].w=0.f;}
        int rb=w*64;
        const float4* base=(const float4*)(inp+((size_t)b*4096+p*512+rb)*128);
        const float* wb=dbuf+rb*17;
        for(int i=0;i<64;i++){
            float4 x=base[i*32+l];
            const float* wr=wb+i*17;
#pragma unroll
            for(int q=0;q<16;q++){
                float wq=wr[q];
                Sa[q].x=fmaf(wq,x.x,Sa[q].x); Sa[q].y=fmaf(wq,x.y,Sa[q].y);
                Sa[q].z=fmaf(wq,x.z,Sa[q].z); Sa[q].w=fmaf(wq,x.w,Sa[q].w);
            }
        }
#pragma unroll
        for(int q=0;q<16;q++){
            atomicAdd(&Sblk[q*128+4*l+0],Sa[q].x);
            atomicAdd(&Sblk[q*128+4*l+1],Sa[q].y);
            atomicAdd(&Sblk[q*128+4*l+2],Sa[q].z);
            atomicAdd(&Sblk[q*128+4*l+3],Sa[q].w);
        }
    }
    __syncthreads();
    float* tp=g_Tpart+((size_t)(b*8+p))*2048;
    for(int i=t;i<2048;i+=256) tp[i]=Sblk[i];
    if(t<16){g_t1p[(b*8+p)*16+t]=t1s[t];g_t2p[(b*8+p)*16+t]=t2s[t];}
}

// ---- fused tail: u-projection + GRU + FFN + next-iter qk. grid 64 x 256 ----
__global__ void __launch_bounds__(256) ktail(const float* __restrict__ Wv,
        const float* __restrict__ gkv, const float* __restrict__ bkv,
        const float* __restrict__ wih, const float* __restrict__ whh,
        const float* __restrict__ bih, const float* __restrict__ bhh,
        const float* __restrict__ g2, const float* __restrict__ b2ln,
        const float* __restrict__ w1, const float* __restrict__ b1,
        const float* __restrict__ w2, const float* __restrict__ b2f,
        const float* __restrict__ gq, const float* __restrict__ bq,
        float* __restrict__ qout, int last){
    int blk=blockIdx.x, b=blk>>1, qh=(blk&1)*8;
    int t=threadIdx.x, w=t>>5, l=t&31;
    __shared__ float Sh[8][128], su[8][128], sx[8][128], sy[8][128], sh1[8][512];
    __shared__ float t1a[8], t2a[8], rsa[8];
    if(t<8){
        float s1=0.f,s2=0.f;
        for(int p=0;p<8;p++){
            s1+=g_t1p[(b*8+p)*16+qh+t];
            s2+=g_t2p[(b*8+p)*16+qh+t];
        }
        t1a[t]=s1; t2a[t]=s2; rsa[t]=1.f/(s2+1e-5f);
    }
#pragma unroll
    for(int k=0;k<4;k++)
        ((float*)sx)[k*256+t]=g_qstate[(b*16+qh)*128+k*256+t];
    __syncthreads();
    // S reduce + kv-LN correction
#pragma unroll
    for(int k=0;k<4;k++){
        int idx=k*256+t, q=idx>>7, c=idx&127;
        float a=0.f;
        for(int p=0;p<8;p++) a+=g_Tpart[((size_t)(b*8+p))*2048+(qh+q)*128+c];
        ((float*)Sh)[idx]=fmaf(gkv[c],a-t1a[q],bkv[c]*t2a[q]);
    }
    __syncthreads();
    // u = Sh @ Wv^T * rs
    {
        int c=t&127, qg=(t>>7)*4;
        float acc[4]={0.f,0.f,0.f,0.f};
        const float4* wr=(const float4*)(Wv+(size_t)c*128);
        for(int d=0;d<32;d++){
            float4 wv=wr[d];
#pragma unroll
            for(int k=0;k<4;k++) acc[k]+=dot4(((const float4*)Sh[qg+k])[d],wv);
        }
#pragma unroll
        for(int k=0;k<4;k++) su[qg+k][c]=acc[k]*rsa[qg+k];
    }
    __syncthreads();
    // GRU -> sy
    {
        int c=t&127, rh=(t>>7)*4;
        float aIR[4]={0,0,0,0},aIZ[4]={0,0,0,0},aIN[4]={0,0,0,0};
        float aHR[4]={0,0,0,0},aHZ[4]={0,0,0,0},aHN[4]={0,0,0,0};
        const float4* wir=(const float4*)(wih+(size_t)c*128);
        const float4* wiz=(const float4*)(wih+(size_t)(c+128)*128);
        const float4* win=(const float4*)(wih+(size_t)(c+256)*128);
        const float4* whr=(const float4*)(whh+(size_t)c*128);
        const float4* whz=(const float4*)(whh+(size_t)(c+128)*128);
        const float4* whn=(const float4*)(whh+(size_t)(c+256)*128);
        for(int d=0;d<32;d++){
            float4 w0=wir[d],w1_=wiz[d],w2_=win[d],w3=whr[d],w4=whz[d],w5=whn[d];
#pragma unroll
            for(int k=0;k<4;k++){
                float4 u4=((const float4*)su[rh+k])[d], x4=((const float4*)sx[rh+k])[d];
                aIR[k]+=dot4(u4,w0); aIZ[k]+=dot4(u4,w1_); aIN[k]+=dot4(u4,w2_);
                aHR[k]+=dot4(x4,w3); aHZ[k]+=dot4(x4,w4); aHN[k]+=dot4(x4,w5);
            }
        }
        float bir=bih[c],biz=bih[c+128],bin=bih[c+256];
        float bhr=bhh[c],bhz=bhh[c+128],bhn=bhh[c+256];
#pragma unroll
        for(int k=0;k<4;k++){
            float rr=1.f/(1.f+fexp(-(aIR[k]+bir+aHR[k]+bhr)));
            float zz=1.f/(1.f+fexp(-(aIZ[k]+biz+aHZ[k]+bhz)));
            float nn=tanhf(aIN[k]+bin+rr*(aHN[k]+bhn));
            sy[rh+k][c]=(1.f-zz)*nn+zz*sx[rh+k][c];
        }
    }
    __syncthreads();
    // LN(y) -> Sh (reused as z)
    ln_rows8(sy,Sh,g2,b2ln,w,l);
    __syncthreads();
    // FFN layer 1 -> sh1
    {
        float acc0[8]={0,0,0,0,0,0,0,0}, acc1[8]={0,0,0,0,0,0,0,0};
        const float4* wa=(const float4*)(w1+(size_t)t*128);
        const float4* wb=(const float4*)(w1+(size_t)(t+256)*128);
        for(int d=0;d<32;d++){
            float4 a=wa[d], bb=wb[d];
#pragma unroll
            for(int r=0;r<8;r++){
                float4 zz=((const float4*)Sh[r])[d];
                acc0[r]+=dot4(zz,a); acc1[r]+=dot4(zz,bb);
            }
        }
        float b0=b1[t], b256=b1[t+256];
#pragma unroll
        for(int r=0;r<8;r++){
            sh1[r][t]=fmaxf(acc0[r]+b0,0.f);
            sh1[r][t+256]=fmaxf(acc1[r]+b256,0.f);
        }
    }
    __syncthreads();
    // FFN layer 2 + residual -> qstate (and out), stash qnew into su
    {
        int c=t&127, rh=(t>>7)*4;
        float acc[4]={0.f,0.f,0.f,0.f};
        const float4* wp=(const float4*)(w2+(size_t)c*512);
        for(int d=0;d<128;d++){
            float4 wv=wp[d];
#pragma unroll
            for(int k=0;k<4;k++) acc[k]+=dot4(((const float4*)sh1[rh+k])[d],wv);
        }
        float bb=b2f[c];
#pragma unroll
        for(int k=0;k<4;k++){
            float val=sy[rh+k][c]+acc[k]+bb;
            g_qstate[(b*16+qh+rh+k)*128+c]=val;
            su[rh+k][c]=val;
            if(last) qout[(b*16+qh+rh+k)*128+c]=val;
        }
    }
    __syncthreads();
    if(last) return;
    // next-iter qk: LN(qnew) -> sy ; @M1*gkv -> qkg, cq1, cq0
    ln_rows8(su,sy,gq,bq,w,l);
    __syncthreads();
    qkproj(sy,Sh,gkv,bkv,b*16+qh,t,w,l);
}

extern "C" void kernel_launch(void* const* d_in, const int* in_sizes, int n_in,
                              void* d_out, int out_size){
    const float* inp=(const float*)d_in[0];
    const float* query=(const float*)d_in[1];
    const float* ln_kv_g=(const float*)d_in[2];
    const float* ln_kv_b=(const float*)d_in[3];
    const float* Wk=(const float*)d_in[4];
    const float* Wv=(const float*)d_in[5];
    const float* ln_q_g=(const float*)d_in[6];
    const float* ln_q_b=(const float*)d_in[7];
    const float* Wq=(const float*)d_in[8];
    const float* gru_wih=(const float*)d_in[9];
    const float* gru_whh=(const float*)d_in[10];
    const float* gru_bih=(const float*)d_in[11];
    const float* gru_bhh=(const float*)d_in[12];
    const float* ln2_g=(const float*)d_in[13];
    const float* ln2_b=(const float*)d_in[14];
    const float* ffn_w1=(const float*)d_in[15];
    const float* ffn_b1=(const float*)d_in[16];
    const float* ffn_w2=(const float*)d_in[17];
    const float* ffn_b2=(const float*)d_in[18];
    float* out=(float*)d_out;
    float* a0out=out+32*16*128;

    kM1<<<128,128>>>(Wq,Wk);
    kcopy<<<512,128>>>(query);
    kqk0<<<64,256>>>(ln_q_g,ln_q_b,ln_kv_g,ln_kv_b);
    for(int it=0;it<3;it++){
        int last=(it==2);
        kstream3<<<dim3(8,32),256>>>(inp,a0out,last);
        ktail<<<64,256>>>(Wv,ln_kv_g,ln_kv_b,gru_wih,gru_whh,gru_bih,gru_bhh,
                          ln2_g,ln2_b,ffn_w1,ffn_b1,ffn_w2,ffn_b2,
                          ln_q_g,ln_q_b,out,last);
    }
}